// round 1
// baseline (speedup 1.0000x reference)
#include <cuda_runtime.h>
#include <math.h>

// Problem constants (Mamba_8641474200045): B=4, T=4096, D=1024
#define BB 4
#define TT 4096
#define DD 1024
#define MROWS (BB * TT)          // 16384

// Scratch (allocation-free rule: __device__ globals)
__device__ float g_proj[(size_t)MROWS * 2 * DD];  // (B*T, 2D) = x@W_in + b_in
__device__ float g_y[(size_t)MROWS * DD];         // gate * ssm(v)

// ---------------------------------------------------------------------------
// Tiled FP32 SGEMM with bias: C[M,N] = A[M,K] @ B[K,N] + bias[N]
// BM=BN=128, BK=16, 256 threads, 8x8 micro-tile per thread.
// ---------------------------------------------------------------------------
template <int BM, int BN, int BK, int TM, int TN>
__global__ __launch_bounds__(256, 2)
void sgemm_bias(const float* __restrict__ Amat,
                const float* __restrict__ Bmat,
                const float* __restrict__ bias,
                float* __restrict__ Cmat,
                int M, int N, int K)
{
    __shared__ float As[BK][BM];   // transposed A tile: As[k][m]
    __shared__ float Bs[BK][BN];   // Bs[k][n]

    const int tid  = threadIdx.x;          // 0..255
    const int bm   = blockIdx.y * BM;
    const int bn   = blockIdx.x * BN;
    const int tcol = tid % (BN / TN);      // 0..15
    const int trow = tid / (BN / TN);      // 0..15

    float acc[TM][TN];
#pragma unroll
    for (int i = 0; i < TM; i++)
#pragma unroll
        for (int j = 0; j < TN; j++) acc[i][j] = 0.0f;

    // A-tile loads: BM x BK floats as float4 => BM * BK/4 = 512 float4, 2/thread
    const int a4_per_row = BK / 4;             // 4
    const int a_row0     = tid / a4_per_row;   // 0..63 (two passes of 64 rows)
    const int a_col4     = tid % a4_per_row;
    // B-tile loads: BK x BN floats as float4 => BK * BN/4 = 512 float4, 2/thread
    const int b4_per_row = BN / 4;             // 32
    const int b_row0     = tid / b4_per_row;   // 0..7 (two passes of 8 rows)
    const int b_col4     = tid % b4_per_row;

    for (int k0 = 0; k0 < K; k0 += BK) {
#pragma unroll
        for (int i = 0; i < 2; ++i) {
            int r = a_row0 + i * 64;
            float4 v = *(const float4*)(&Amat[(size_t)(bm + r) * K + k0 + a_col4 * 4]);
            As[a_col4 * 4 + 0][r] = v.x;
            As[a_col4 * 4 + 1][r] = v.y;
            As[a_col4 * 4 + 2][r] = v.z;
            As[a_col4 * 4 + 3][r] = v.w;
        }
#pragma unroll
        for (int i = 0; i < 2; ++i) {
            int r = b_row0 + i * 8;
            *(float4*)(&Bs[r][b_col4 * 4]) =
                *(const float4*)(&Bmat[(size_t)(k0 + r) * N + bn + b_col4 * 4]);
        }
        __syncthreads();

#pragma unroll
        for (int kk = 0; kk < BK; ++kk) {
            float a[TM], b[TN];
#pragma unroll
            for (int i = 0; i < TM; i += 4) {
                float4 v = *(const float4*)(&As[kk][trow * TM + i]);
                a[i] = v.x; a[i+1] = v.y; a[i+2] = v.z; a[i+3] = v.w;
            }
#pragma unroll
            for (int j = 0; j < TN; j += 4) {
                float4 v = *(const float4*)(&Bs[kk][tcol * TN + j]);
                b[j] = v.x; b[j+1] = v.y; b[j+2] = v.z; b[j+3] = v.w;
            }
#pragma unroll
            for (int i = 0; i < TM; i++)
#pragma unroll
                for (int j = 0; j < TN; j++)
                    acc[i][j] += a[i] * b[j];
        }
        __syncthreads();
    }

    // Epilogue: add bias, vectorized store
#pragma unroll
    for (int i = 0; i < TM; i++) {
        int row = bm + trow * TM + i;
#pragma unroll
        for (int j = 0; j < TN; j += 4) {
            int col = bn + tcol * TN + j;
            float4 v;
            v.x = acc[i][j + 0] + bias[col + 0];
            v.y = acc[i][j + 1] + bias[col + 1];
            v.z = acc[i][j + 2] + bias[col + 2];
            v.w = acc[i][j + 3] + bias[col + 3];
            *(float4*)(&Cmat[(size_t)row * N + col]) = v;
        }
    }
}

// ---------------------------------------------------------------------------
// Fused sigmoid(gate) * C * scan(v):  one thread per (b, d) series.
// proj layout: (B*T, 2D), v = cols [0,D), gate = cols [D,2D).
// h_t = sigmoid(A_d) * h_{t-1} + v_t;  y_t = sigmoid(gate_t) * C_d * h_t
// Consecutive threads -> consecutive d -> fully coalesced per step.
// ---------------------------------------------------------------------------
__global__ __launch_bounds__(256)
void scan_gate_kernel(const float* __restrict__ A,
                      const float* __restrict__ C)
{
    int idx = blockIdx.x * blockDim.x + threadIdx.x;   // 0 .. B*D-1
    if (idx >= BB * DD) return;
    int b = idx / DD;
    int d = idx % DD;

    const float decay = 1.0f / (1.0f + expf(-A[d]));
    const float c     = C[d];

    const float* vp = g_proj + (size_t)b * TT * 2 * DD + d;
    const float* gp = vp + DD;
    float*       yp = g_y   + (size_t)b * TT * DD + d;

    float h = 0.0f;
#pragma unroll 4
    for (int t = 0; t < TT; ++t) {
        float v = __ldg(&vp[(size_t)t * 2 * DD]);
        float g = __ldg(&gp[(size_t)t * 2 * DD]);
        h = fmaf(decay, h, v);
        float gate = 1.0f / (1.0f + expf(-g));
        yp[(size_t)t * DD] = gate * c * h;
    }
}

// ---------------------------------------------------------------------------
// Launch
// ---------------------------------------------------------------------------
extern "C" void kernel_launch(void* const* d_in, const int* in_sizes, int n_in,
                              void* d_out, int out_size)
{
    const float* x     = (const float*)d_in[0];  // (B,T,D)
    const float* W_in  = (const float*)d_in[1];  // (D, 2D)
    const float* b_in  = (const float*)d_in[2];  // (2D,)
    const float* A     = (const float*)d_in[3];  // (D,)
    const float* C     = (const float*)d_in[4];  // (D,)
    const float* W_out = (const float*)d_in[5];  // (D, D)
    const float* b_out = (const float*)d_in[6];  // (D,)
    float*       out   = (float*)d_out;          // (B,T,D)

    float* proj_ptr = nullptr;
    float* y_ptr    = nullptr;
    cudaGetSymbolAddress((void**)&proj_ptr, g_proj);
    cudaGetSymbolAddress((void**)&y_ptr, g_y);

    // GEMM1: proj = x @ W_in + b_in   (M=16384, N=2048, K=1024)
    {
        dim3 grid((2 * DD) / 128, MROWS / 128);
        sgemm_bias<128, 128, 16, 8, 8><<<grid, 256>>>(
            x, W_in, b_in, proj_ptr, MROWS, 2 * DD, DD);
    }

    // Fused sigmoid + SSM scan + gate + C
    {
        int n = BB * DD;
        scan_gate_kernel<<<(n + 255) / 256, 256>>>(A, C);
    }

    // GEMM2: out = y @ W_out + b_out  (M=16384, N=1024, K=1024)
    {
        dim3 grid(DD / 128, MROWS / 128);
        sgemm_bias<128, 128, 16, 8, 8><<<grid, 256>>>(
            y_ptr, W_out, b_out, out, MROWS, DD, DD);
    }
}

// round 11
// speedup vs baseline: 1.3283x; 1.3283x over previous
#include <cuda_runtime.h>
#include <cstdint>
#include <math.h>

// Problem constants (Mamba_8641474200045): B=4, T=4096, D=1024
#define BB 4
#define TT 4096
#define DD 1024
#define MROWS (BB * TT)          // 16384

// ---------------------------------------------------------------------------
// Scratch (allocation-free rule: __device__ globals)
// ---------------------------------------------------------------------------
__device__ float g_proj[(size_t)MROWS * 2 * DD];   // (B*T, 2D)
__device__ float g_y[(size_t)MROWS * DD];          // gate * ssm(v)
__device__ float g_wt_in[(size_t)(2 * DD) * DD];   // W_in^T  (2D, D) K-major
__device__ float g_wt_out[(size_t)DD * DD];        // W_out^T (D, D)  K-major

// ---------------------------------------------------------------------------
// tf32 helpers
// ---------------------------------------------------------------------------
__device__ __forceinline__ uint32_t f32_to_tf32(float x) {
    uint32_t r;
    asm("cvt.rna.tf32.f32 %0, %1;" : "=r"(r) : "f"(x));
    return r;
}

__device__ __forceinline__ void mma_16n8k8_tf32(float* d,            // 4
                                                const uint32_t* a,   // 4
                                                const uint32_t* b)   // 2
{
    asm volatile(
        "mma.sync.aligned.m16n8k8.row.col.f32.tf32.tf32.f32 "
        "{%0, %1, %2, %3}, {%4, %5, %6, %7}, {%8, %9}, {%0, %1, %2, %3};"
        : "+f"(d[0]), "+f"(d[1]), "+f"(d[2]), "+f"(d[3])
        : "r"(a[0]), "r"(a[1]), "r"(a[2]), "r"(a[3]), "r"(b[0]), "r"(b[1]));
}

// ---------------------------------------------------------------------------
// Pipelined tf32 mma.sync GEMM with bias:
//   C[M,N] = A[M,K] @ Bt[N,K]^T + bias[N]
// BM=BN=128, BK=32, 256 threads, 8 warps (2 m x 4 n), warp tile 64x32.
// Smem: double-buffered A[128][36], B[128][36] (pad 36 -> conflict-free frags).
// ---------------------------------------------------------------------------
#define BM 128
#define BN 128
#define BK 32
#define LDS_PAD 36
#define TILE_FLOATS (BM * LDS_PAD)                 // per tile (A or B)
#define GEMM_SMEM_BYTES (2 * 2 * TILE_FLOATS * 4)  // 2 bufs x (A+B) = 73728

__global__ __launch_bounds__(256, 1)
void gemm_mma(const float* __restrict__ Amat,
              const float* __restrict__ Bt,     // (N, K) K-major
              const float* __restrict__ bias,
              float* __restrict__ Cmat,
              int N, int K)
{
    extern __shared__ float smem[];
    float* As = smem;                       // [2][BM][LDS_PAD]
    float* Bs = smem + 2 * TILE_FLOATS;     // [2][BN][LDS_PAD]

    const int tid = threadIdx.x;
    const int wid = tid >> 5;
    const int lane = tid & 31;
    const int wm = (wid >> 2) * 64;         // warp m offset (0 / 64)
    const int wn = (wid & 3) * 32;          // warp n offset (0/32/64/96)
    const int bm = blockIdx.y * BM;
    const int bn = blockIdx.x * BN;

    // Loader mapping: 2 threads per row, 16 k each (4 x float4)
    const int lrow = tid >> 1;              // 0..127
    const int lk = (tid & 1) * 16;          // 0 or 16

    const float* ga = Amat + (size_t)(bm + lrow) * K + lk;
    const float* gb = Bt + (size_t)(bn + lrow) * K + lk;
    float* sa = As + lrow * LDS_PAD + lk;
    float* sb = Bs + lrow * LDS_PAD + lk;

    float acc[4][4][4];                     // [mt][nt][frag]
#pragma unroll
    for (int i = 0; i < 4; i++)
#pragma unroll
        for (int j = 0; j < 4; j++)
#pragma unroll
            for (int r = 0; r < 4; r++) acc[i][j][r] = 0.0f;

    const int NIT = K / BK;

    // Prologue: load tile 0 into buffer 0
    {
        float4 ra[4], rb[4];
#pragma unroll
        for (int q = 0; q < 4; ++q) {
            ra[q] = *(const float4*)(ga + q * 4);
            rb[q] = *(const float4*)(gb + q * 4);
        }
#pragma unroll
        for (int q = 0; q < 4; ++q) {
            sa[q * 4 + 0] = __uint_as_float(f32_to_tf32(ra[q].x));
            sa[q * 4 + 1] = __uint_as_float(f32_to_tf32(ra[q].y));
            sa[q * 4 + 2] = __uint_as_float(f32_to_tf32(ra[q].z));
            sa[q * 4 + 3] = __uint_as_float(f32_to_tf32(ra[q].w));
            sb[q * 4 + 0] = __uint_as_float(f32_to_tf32(rb[q].x));
            sb[q * 4 + 1] = __uint_as_float(f32_to_tf32(rb[q].y));
            sb[q * 4 + 2] = __uint_as_float(f32_to_tf32(rb[q].z));
            sb[q * 4 + 3] = __uint_as_float(f32_to_tf32(rb[q].w));
        }
    }
    __syncthreads();

    for (int it = 0; it < NIT; ++it) {
        const int buf = it & 1;
        const float* a_s = As + buf * TILE_FLOATS;
        const float* b_s = Bs + buf * TILE_FLOATS;

        // Prefetch next tile into registers
        float4 ra[4], rb[4];
        if (it + 1 < NIT) {
            const float* gan = ga + (it + 1) * BK;
            const float* gbn = gb + (it + 1) * BK;
#pragma unroll
            for (int q = 0; q < 4; ++q) {
                ra[q] = *(const float4*)(gan + q * 4);
                rb[q] = *(const float4*)(gbn + q * 4);
            }
        }

        // Compute current tile: 4 k-steps of 8
#pragma unroll
        for (int ks = 0; ks < 4; ++ks) {
            const int k8 = ks * 8;
            uint32_t afr[4][4], bfr[4][2];
            const int ar = lane >> 2;       // 0..7
            const int ac = lane & 3;        // 0..3
#pragma unroll
            for (int mt = 0; mt < 4; ++mt) {
                const float* ap = a_s + (wm + mt * 16 + ar) * LDS_PAD + k8 + ac;
                afr[mt][0] = __float_as_uint(ap[0]);
                afr[mt][1] = __float_as_uint(ap[8 * LDS_PAD]);
                afr[mt][2] = __float_as_uint(ap[4]);
                afr[mt][3] = __float_as_uint(ap[8 * LDS_PAD + 4]);
            }
#pragma unroll
            for (int nt = 0; nt < 4; ++nt) {
                const float* bp = b_s + (wn + nt * 8 + ar) * LDS_PAD + k8 + ac;
                bfr[nt][0] = __float_as_uint(bp[0]);
                bfr[nt][1] = __float_as_uint(bp[4]);
            }
#pragma unroll
            for (int mt = 0; mt < 4; ++mt)
#pragma unroll
                for (int nt = 0; nt < 4; ++nt)
                    mma_16n8k8_tf32(acc[mt][nt], afr[mt], bfr[nt]);
        }

        // Store prefetched tile into the other buffer
        if (it + 1 < NIT) {
            float* san = sa + ((it + 1) & 1) * TILE_FLOATS;
            float* sbn = sb + ((it + 1) & 1) * TILE_FLOATS;
#pragma unroll
            for (int q = 0; q < 4; ++q) {
                san[q * 4 + 0] = __uint_as_float(f32_to_tf32(ra[q].x));
                san[q * 4 + 1] = __uint_as_float(f32_to_tf32(ra[q].y));
                san[q * 4 + 2] = __uint_as_float(f32_to_tf32(ra[q].z));
                san[q * 4 + 3] = __uint_as_float(f32_to_tf32(ra[q].w));
                sbn[q * 4 + 0] = __uint_as_float(f32_to_tf32(rb[q].x));
                sbn[q * 4 + 1] = __uint_as_float(f32_to_tf32(rb[q].y));
                sbn[q * 4 + 2] = __uint_as_float(f32_to_tf32(rb[q].z));
                sbn[q * 4 + 3] = __uint_as_float(f32_to_tf32(rb[q].w));
            }
        }
        __syncthreads();
    }

    // Epilogue: D frag layout: c0,c1 at (row=lane>>2, col=2*(lane&3)+{0,1}),
    // c2,c3 at row+8.
#pragma unroll
    for (int mt = 0; mt < 4; ++mt) {
        const int r0 = bm + wm + mt * 16 + (lane >> 2);
#pragma unroll
        for (int nt = 0; nt < 4; ++nt) {
            const int c0 = bn + wn + nt * 8 + 2 * (lane & 3);
            const float bx = bias[c0], by = bias[c0 + 1];
            float2 v0 = make_float2(acc[mt][nt][0] + bx, acc[mt][nt][1] + by);
            float2 v1 = make_float2(acc[mt][nt][2] + bx, acc[mt][nt][3] + by);
            *(float2*)(Cmat + (size_t)r0 * N + c0) = v0;
            *(float2*)(Cmat + (size_t)(r0 + 8) * N + c0) = v1;
        }
    }
}

// ---------------------------------------------------------------------------
// 32x32 tiled transpose: Wt[n][k] = W[k][n].  W: (K, N)
// ---------------------------------------------------------------------------
__global__ __launch_bounds__(256)
void transpose_w(const float* __restrict__ W, float* __restrict__ Wt, int K, int N)
{
    __shared__ float tile[32][33];
    int bx = blockIdx.x * 32;  // n
    int by = blockIdx.y * 32;  // k
    int x = threadIdx.x, y = threadIdx.y;
#pragma unroll
    for (int i = 0; i < 32; i += 8)
        tile[y + i][x] = W[(size_t)(by + y + i) * N + bx + x];
    __syncthreads();
#pragma unroll
    for (int i = 0; i < 32; i += 8)
        Wt[(size_t)(bx + y + i) * K + by + x] = tile[x][y + i];
}

// ---------------------------------------------------------------------------
// Fused sigmoid(gate) * C * scan(v): one thread per (b, d) series.
// ---------------------------------------------------------------------------
__global__ __launch_bounds__(256)
void scan_gate_kernel(const float* __restrict__ A, const float* __restrict__ C)
{
    int idx = blockIdx.x * blockDim.x + threadIdx.x;
    if (idx >= BB * DD) return;
    int b = idx / DD;
    int d = idx % DD;

    const float decay = 1.0f / (1.0f + expf(-A[d]));
    const float c = C[d];

    const float* vp = g_proj + (size_t)b * TT * 2 * DD + d;
    const float* gp = vp + DD;
    float* yp = g_y + (size_t)b * TT * DD + d;

    float h = 0.0f;
#pragma unroll 4
    for (int t = 0; t < TT; ++t) {
        float v = __ldg(&vp[(size_t)t * 2 * DD]);
        float g = __ldg(&gp[(size_t)t * 2 * DD]);
        h = fmaf(decay, h, v);
        float gate = 1.0f / (1.0f + expf(-g));
        yp[(size_t)t * DD] = gate * c * h;
    }
}

// ---------------------------------------------------------------------------
// Launch
// ---------------------------------------------------------------------------
extern "C" void kernel_launch(void* const* d_in, const int* in_sizes, int n_in,
                              void* d_out, int out_size)
{
    const float* x     = (const float*)d_in[0];
    const float* W_in  = (const float*)d_in[1];
    const float* b_in  = (const float*)d_in[2];
    const float* A     = (const float*)d_in[3];
    const float* C     = (const float*)d_in[4];
    const float* W_out = (const float*)d_in[5];
    const float* b_out = (const float*)d_in[6];
    float*       out   = (float*)d_out;

    float *proj_ptr, *y_ptr, *wtin_ptr, *wtout_ptr;
    cudaGetSymbolAddress((void**)&proj_ptr, g_proj);
    cudaGetSymbolAddress((void**)&y_ptr, g_y);
    cudaGetSymbolAddress((void**)&wtin_ptr, g_wt_in);
    cudaGetSymbolAddress((void**)&wtout_ptr, g_wt_out);

    static int smem_set = 0;
    if (!smem_set) {
        cudaFuncSetAttribute(gemm_mma, cudaFuncAttributeMaxDynamicSharedMemorySize,
                             GEMM_SMEM_BYTES);
        smem_set = 1;
    }

    // Transpose weights to K-major (N, K)
    {
        dim3 blk(32, 8);
        transpose_w<<<dim3((2 * DD) / 32, DD / 32), blk>>>(W_in, wtin_ptr, DD, 2 * DD);
        transpose_w<<<dim3(DD / 32, DD / 32), blk>>>(W_out, wtout_ptr, DD, DD);
    }

    // GEMM1: proj = x @ W_in + b_in   (M=16384, N=2048, K=1024)
    gemm_mma<<<dim3((2 * DD) / BN, MROWS / BM), 256, GEMM_SMEM_BYTES>>>(
        x, wtin_ptr, b_in, proj_ptr, 2 * DD, DD);

    // Fused sigmoid + SSM scan + gate + C
    scan_gate_kernel<<<(BB * DD + 255) / 256, 256>>>(A, C);

    // GEMM2: out = y @ W_out + b_out  (M=16384, N=1024, K=1024)
    gemm_mma<<<dim3(DD / BN, MROWS / BM), 256, GEMM_SMEM_BYTES>>>(
        y_ptr, wtout_ptr, b_out, out, DD, DD);
}

// round 14
// speedup vs baseline: 1.4018x; 1.0554x over previous
#include <cuda_runtime.h>
#include <cstdint>
#include <math.h>

// Problem constants (Mamba_8641474200045): B=4, T=4096, D=1024
#define BB 4
#define TT 4096
#define DD 1024
#define MROWS (BB * TT)          // 16384

// ---------------------------------------------------------------------------
// Scratch (allocation-free rule: __device__ globals)
// ---------------------------------------------------------------------------
__device__ float g_proj[(size_t)MROWS * 2 * DD];   // (B*T, 2D)
__device__ float g_y[(size_t)MROWS * DD];          // gate * ssm(v)

// ---------------------------------------------------------------------------
// tf32 helpers
// ---------------------------------------------------------------------------
__device__ __forceinline__ uint32_t f32_to_tf32(float x) {
    uint32_t r;
    asm("cvt.rna.tf32.f32 %0, %1;" : "=r"(r) : "f"(x));
    return r;
}

__device__ __forceinline__ void mma_16n8k8_tf32(float* d,            // 4
                                                const uint32_t* a,   // 4
                                                const uint32_t* b)   // 2
{
    asm volatile(
        "mma.sync.aligned.m16n8k8.row.col.f32.tf32.tf32.f32 "
        "{%0, %1, %2, %3}, {%4, %5, %6, %7}, {%8, %9}, {%0, %1, %2, %3};"
        : "+f"(d[0]), "+f"(d[1]), "+f"(d[2]), "+f"(d[3])
        : "r"(a[0]), "r"(a[1]), "r"(a[2]), "r"(a[3]), "r"(b[0]), "r"(b[1]));
}

// ---------------------------------------------------------------------------
// Pipelined tf32 mma.sync GEMM with bias:
//   C[M,N] = A[M,K] @ W[K,N] + bias[N]     (W read in native (K,N) layout)
// BM=BN=128, BK=32, 256 threads, 8 warps (2 m x 4 n), warp tile 64x32.
// Smem: A[2][128][36] K-major (pad 36 -> conflict-free A frags);
//       B[2][32][136] N-major (pad 136 = 8 mod 32 -> conflict-free B frags).
// ---------------------------------------------------------------------------
#define BM 128
#define BN 128
#define BK 32
#define A_PAD 36
#define B_PAD 136
#define A_TILE_FLOATS (BM * A_PAD)                 // 4608
#define B_TILE_FLOATS (BK * B_PAD)                 // 4352
#define GEMM_SMEM_BYTES ((2 * A_TILE_FLOATS + 2 * B_TILE_FLOATS) * 4)  // 71680

__global__ __launch_bounds__(256, 1)
void gemm_mma(const float* __restrict__ Amat,
              const float* __restrict__ Wkn,    // (K, N) row-major
              const float* __restrict__ bias,
              float* __restrict__ Cmat,
              int N, int K)
{
    extern __shared__ float smem[];
    float* As = smem;                            // [2][BM][A_PAD]
    float* Bs = smem + 2 * A_TILE_FLOATS;        // [2][BK][B_PAD]

    const int tid = threadIdx.x;
    const int wid = tid >> 5;
    const int lane = tid & 31;
    const int wm = (wid >> 2) * 64;              // warp m offset (0 / 64)
    const int wn = (wid & 3) * 32;               // warp n offset (0/32/64/96)
    const int bm = blockIdx.y * BM;
    const int bn = blockIdx.x * BN;

    // A loader mapping: 2 threads per row, 16 k each (4 x float4)
    const int lrow = tid >> 1;                   // 0..127
    const int lk = (tid & 1) * 16;               // 0 or 16
    const float* ga = Amat + (size_t)(bm + lrow) * K + lk;
    float* sa = As + lrow * A_PAD + lk;

    // B loader mapping: warp w covers k-row (wid + 8p), lane covers 4 n's.
    const float* gb = Wkn + (size_t)wid * N + bn + lane * 4;
    float* sb = Bs + wid * B_PAD + lane * 4;

    float acc[4][4][4];                          // [mt][nt][frag]
#pragma unroll
    for (int i = 0; i < 4; i++)
#pragma unroll
        for (int j = 0; j < 4; j++)
#pragma unroll
            for (int r = 0; r < 4; r++) acc[i][j][r] = 0.0f;

    const int NIT = K / BK;

    // Prologue: load tile 0 into buffer 0
    {
        float4 ra[4], rb[4];
#pragma unroll
        for (int q = 0; q < 4; ++q) {
            ra[q] = *(const float4*)(ga + q * 4);
            rb[q] = *(const float4*)(gb + (size_t)(8 * q) * N);
        }
#pragma unroll
        for (int q = 0; q < 4; ++q) {
            sa[q * 4 + 0] = __uint_as_float(f32_to_tf32(ra[q].x));
            sa[q * 4 + 1] = __uint_as_float(f32_to_tf32(ra[q].y));
            sa[q * 4 + 2] = __uint_as_float(f32_to_tf32(ra[q].z));
            sa[q * 4 + 3] = __uint_as_float(f32_to_tf32(ra[q].w));
            float4 s;
            s.x = __uint_as_float(f32_to_tf32(rb[q].x));
            s.y = __uint_as_float(f32_to_tf32(rb[q].y));
            s.z = __uint_as_float(f32_to_tf32(rb[q].z));
            s.w = __uint_as_float(f32_to_tf32(rb[q].w));
            *(float4*)(sb + (8 * q) * B_PAD) = s;
        }
    }
    __syncthreads();

    for (int it = 0; it < NIT; ++it) {
        const int buf = it & 1;
        const float* a_s = As + buf * A_TILE_FLOATS;
        const float* b_s = Bs + buf * B_TILE_FLOATS;

        // Prefetch next tile into registers
        float4 ra[4], rb[4];
        if (it + 1 < NIT) {
            const float* gan = ga + (it + 1) * BK;
            const float* gbn = gb + (size_t)(it + 1) * BK * N;
#pragma unroll
            for (int q = 0; q < 4; ++q) {
                ra[q] = *(const float4*)(gan + q * 4);
                rb[q] = *(const float4*)(gbn + (size_t)(8 * q) * N);
            }
        }

        // Compute current tile: 4 k-steps of 8
#pragma unroll
        for (int ks = 0; ks < 4; ++ks) {
            const int k8 = ks * 8;
            uint32_t afr[4][4], bfr[4][2];
            const int ar = lane >> 2;            // 0..7
            const int ac = lane & 3;             // 0..3
#pragma unroll
            for (int mt = 0; mt < 4; ++mt) {
                const float* ap = a_s + (wm + mt * 16 + ar) * A_PAD + k8 + ac;
                afr[mt][0] = __float_as_uint(ap[0]);
                afr[mt][1] = __float_as_uint(ap[8 * A_PAD]);
                afr[mt][2] = __float_as_uint(ap[4]);
                afr[mt][3] = __float_as_uint(ap[8 * A_PAD + 4]);
            }
            // B frag (col-major): b0 = B[k8+ac][n], b1 = B[k8+ac+4][n]
#pragma unroll
            for (int nt = 0; nt < 4; ++nt) {
                const float* bp = b_s + (k8 + ac) * B_PAD + wn + nt * 8 + ar;
                bfr[nt][0] = __float_as_uint(bp[0]);
                bfr[nt][1] = __float_as_uint(bp[4 * B_PAD]);
            }
#pragma unroll
            for (int mt = 0; mt < 4; ++mt)
#pragma unroll
                for (int nt = 0; nt < 4; ++nt)
                    mma_16n8k8_tf32(acc[mt][nt], afr[mt], bfr[nt]);
        }

        // Store prefetched tile into the other buffer
        if (it + 1 < NIT) {
            const int nb = (it + 1) & 1;
            float* san = sa + nb * A_TILE_FLOATS;
            float* sbn = sb + nb * B_TILE_FLOATS;
#pragma unroll
            for (int q = 0; q < 4; ++q) {
                san[q * 4 + 0] = __uint_as_float(f32_to_tf32(ra[q].x));
                san[q * 4 + 1] = __uint_as_float(f32_to_tf32(ra[q].y));
                san[q * 4 + 2] = __uint_as_float(f32_to_tf32(ra[q].z));
                san[q * 4 + 3] = __uint_as_float(f32_to_tf32(ra[q].w));
                float4 s;
                s.x = __uint_as_float(f32_to_tf32(rb[q].x));
                s.y = __uint_as_float(f32_to_tf32(rb[q].y));
                s.z = __uint_as_float(f32_to_tf32(rb[q].z));
                s.w = __uint_as_float(f32_to_tf32(rb[q].w));
                *(float4*)(sbn + (8 * q) * B_PAD) = s;
            }
        }
        __syncthreads();
    }

    // Epilogue: D frag layout: c0,c1 at (row=lane>>2, col=2*(lane&3)+{0,1}),
    // c2,c3 at row+8.
#pragma unroll
    for (int mt = 0; mt < 4; ++mt) {
        const int r0 = bm + wm + mt * 16 + (lane >> 2);
#pragma unroll
        for (int nt = 0; nt < 4; ++nt) {
            const int c0 = bn + wn + nt * 8 + 2 * (lane & 3);
            const float bx = bias[c0], by = bias[c0 + 1];
            float2 v0 = make_float2(acc[mt][nt][0] + bx, acc[mt][nt][1] + by);
            float2 v1 = make_float2(acc[mt][nt][2] + bx, acc[mt][nt][3] + by);
            *(float2*)(Cmat + (size_t)r0 * N + c0) = v0;
            *(float2*)(Cmat + (size_t)(r0 + 8) * N + c0) = v1;
        }
    }
}

// ---------------------------------------------------------------------------
// Fused sigmoid(gate) * C * scan(v): one thread per (b, d) series.
// ---------------------------------------------------------------------------
__global__ __launch_bounds__(256)
void scan_gate_kernel(const float* __restrict__ A, const float* __restrict__ C)
{
    int idx = blockIdx.x * blockDim.x + threadIdx.x;
    if (idx >= BB * DD) return;
    int b = idx / DD;
    int d = idx % DD;

    const float decay = 1.0f / (1.0f + expf(-A[d]));
    const float c = C[d];

    const float* vp = g_proj + (size_t)b * TT * 2 * DD + d;
    const float* gp = vp + DD;
    float* yp = g_y + (size_t)b * TT * DD + d;

    float h = 0.0f;
#pragma unroll 4
    for (int t = 0; t < TT; ++t) {
        float v = __ldg(&vp[(size_t)t * 2 * DD]);
        float g = __ldg(&gp[(size_t)t * 2 * DD]);
        h = fmaf(decay, h, v);
        float gate = 1.0f / (1.0f + expf(-g));
        yp[(size_t)t * DD] = gate * c * h;
    }
}

// ---------------------------------------------------------------------------
// Launch
// ---------------------------------------------------------------------------
extern "C" void kernel_launch(void* const* d_in, const int* in_sizes, int n_in,
                              void* d_out, int out_size)
{
    const float* x     = (const float*)d_in[0];
    const float* W_in  = (const float*)d_in[1];
    const float* b_in  = (const float*)d_in[2];
    const float* A     = (const float*)d_in[3];
    const float* C     = (const float*)d_in[4];
    const float* W_out = (const float*)d_in[5];
    const float* b_out = (const float*)d_in[6];
    float*       out   = (float*)d_out;

    float *proj_ptr, *y_ptr;
    cudaGetSymbolAddress((void**)&proj_ptr, g_proj);
    cudaGetSymbolAddress((void**)&y_ptr, g_y);

    static int smem_set = 0;
    if (!smem_set) {
        cudaFuncSetAttribute(gemm_mma, cudaFuncAttributeMaxDynamicSharedMemorySize,
                             GEMM_SMEM_BYTES);
        smem_set = 1;
    }

    // GEMM1: proj = x @ W_in + b_in   (M=16384, N=2048, K=1024)
    gemm_mma<<<dim3((2 * DD) / BN, MROWS / BM), 256, GEMM_SMEM_BYTES>>>(
        x, W_in, b_in, proj_ptr, 2 * DD, DD);

    // Fused sigmoid + SSM scan + gate + C
    scan_gate_kernel<<<(BB * DD + 255) / 256, 256>>>(A, C);

    // GEMM2: out = y @ W_out + b_out  (M=16384, N=1024, K=1024)
    gemm_mma<<<dim3(DD / BN, MROWS / BM), 256, GEMM_SMEM_BYTES>>>(
        y_ptr, W_out, b_out, out, DD, DD);
}

// round 15
// speedup vs baseline: 6.0688x; 4.3293x over previous
#include <cuda_runtime.h>
#include <cstdint>
#include <math.h>

// Problem constants (Mamba_8641474200045): B=4, T=4096, D=1024
#define BB 4
#define TT 4096
#define DD 1024
#define MROWS (BB * TT)          // 16384
#define NCHUNK 64
#define CLEN 64                  // TT / NCHUNK

// ---------------------------------------------------------------------------
// Scratch (allocation-free rule: __device__ globals)
// ---------------------------------------------------------------------------
__device__ float g_proj[(size_t)MROWS * 2 * DD];   // (B*T, 2D)
__device__ float g_y[(size_t)MROWS * DD];          // gate * ssm(v)
__device__ float g_carry[(size_t)BB * NCHUNK * DD]; // scan chunk carries / states

// ---------------------------------------------------------------------------
// tf32 / cp.async helpers
// ---------------------------------------------------------------------------
__device__ __forceinline__ uint32_t f32_to_tf32(float x) {
    uint32_t r;
    asm("cvt.rna.tf32.f32 %0, %1;" : "=r"(r) : "f"(x));
    return r;
}

__device__ __forceinline__ uint32_t smem_u32(const void* p) {
    uint32_t a;
    asm("{ .reg .u64 t; cvta.to.shared.u64 t, %1; cvt.u32.u64 %0, t; }" : "=r"(a) : "l"(p));
    return a;
}

#define CP_ASYNC16(sp, gp) \
    asm volatile("cp.async.cg.shared.global [%0], [%1], 16;" :: "r"(sp), "l"(gp))
#define CP_COMMIT() asm volatile("cp.async.commit_group;" ::: "memory")
#define CP_WAIT1()  asm volatile("cp.async.wait_group 1;" ::: "memory")

__device__ __forceinline__ void mma_16n8k8_tf32(float* d,            // 4
                                                const uint32_t* a,   // 4
                                                const uint32_t* b)   // 2
{
    asm volatile(
        "mma.sync.aligned.m16n8k8.row.col.f32.tf32.tf32.f32 "
        "{%0, %1, %2, %3}, {%4, %5, %6, %7}, {%8, %9}, {%0, %1, %2, %3};"
        : "+f"(d[0]), "+f"(d[1]), "+f"(d[2]), "+f"(d[3])
        : "r"(a[0]), "r"(a[1]), "r"(a[2]), "r"(a[3]), "r"(b[0]), "r"(b[1]));
}

// ---------------------------------------------------------------------------
// cp.async 3-stage pipelined tf32 mma.sync GEMM with bias:
//   C[M,N] = A[M,K] @ W[K,N] + bias[N]   (W native (K,N); raw f32 in smem,
//   cvt.rna.tf32 applied after fragment LDS — same operand values as before)
// BM=BN=128, BK=32, 256 threads, 8 warps (2 m x 4 n), warp tile 64x32.
// 2 CTAs/SM via __launch_bounds__(256,2).
// ---------------------------------------------------------------------------
#define BM 128
#define BN 128
#define BK 32
#define A_PAD 36
#define B_PAD 136
#define A_TILE_FLOATS (BM * A_PAD)                 // 4608
#define B_TILE_FLOATS (BK * B_PAD)                 // 4352
#define A_TILE_BYTES (A_TILE_FLOATS * 4)           // 18432
#define B_TILE_BYTES (B_TILE_FLOATS * 4)           // 17408
#define STAGE_FLOATS (A_TILE_FLOATS + B_TILE_FLOATS)
#define STAGE_BYTES (STAGE_FLOATS * 4)             // 35840
#define NSTAGE 3
#define GEMM_SMEM_BYTES (NSTAGE * STAGE_BYTES)     // 107520

__device__ __forceinline__ void issue_stage(uint32_t sstage,
                                            const float* __restrict__ Amat,
                                            const float* __restrict__ Wkn,
                                            int bm, int bn, int k0,
                                            int N, int K, int tid)
{
    // A tile: 128 rows x 128B = 1024 x 16B chunks, 4 per thread
#pragma unroll
    for (int i = 0; i < 4; ++i) {
        int c = tid + 256 * i;
        int row = c >> 3, c8 = c & 7;
        const float* gp = Amat + (size_t)(bm + row) * K + k0 + c8 * 4;
        CP_ASYNC16(sstage + (row * A_PAD + c8 * 4) * 4, gp);
    }
    // B tile: 32 rows x 512B = 1024 x 16B chunks, 4 per thread
#pragma unroll
    for (int i = 0; i < 4; ++i) {
        int c = tid + 256 * i;
        int krow = c >> 5, c16 = c & 31;
        const float* gp = Wkn + (size_t)(k0 + krow) * N + bn + c16 * 4;
        CP_ASYNC16(sstage + A_TILE_BYTES + (krow * B_PAD + c16 * 4) * 4, gp);
    }
}

__global__ __launch_bounds__(256, 2)
void gemm_mma(const float* __restrict__ Amat,
              const float* __restrict__ Wkn,    // (K, N) row-major
              const float* __restrict__ bias,
              float* __restrict__ Cmat,
              int N, int K)
{
    extern __shared__ float smem[];
    const uint32_t sbase = smem_u32(smem);

    const int tid = threadIdx.x;
    const int wid = tid >> 5;
    const int lane = tid & 31;
    const int wm = (wid >> 2) * 64;              // warp m offset (0 / 64)
    const int wn = (wid & 3) * 32;               // warp n offset (0/32/64/96)
    const int bm = blockIdx.y * BM;
    const int bn = blockIdx.x * BN;

    float acc[4][4][4];                          // [mt][nt][frag]
#pragma unroll
    for (int i = 0; i < 4; i++)
#pragma unroll
        for (int j = 0; j < 4; j++)
#pragma unroll
            for (int r = 0; r < 4; r++) acc[i][j][r] = 0.0f;

    const int NIT = K / BK;                      // 32

    // Prologue: stages 0, 1 in flight
    issue_stage(sbase + 0 * STAGE_BYTES, Amat, Wkn, bm, bn, 0 * BK, N, K, tid);
    CP_COMMIT();
    issue_stage(sbase + 1 * STAGE_BYTES, Amat, Wkn, bm, bn, 1 * BK, N, K, tid);
    CP_COMMIT();

    for (int it = 0; it < NIT; ++it) {
        CP_WAIT1();                              // stage it complete (this thread)
        __syncthreads();                         // all threads' stage it visible;
                                                 // all done computing stage it-1
        if (it + 2 < NIT)
            issue_stage(sbase + ((it + 2) % NSTAGE) * STAGE_BYTES,
                        Amat, Wkn, bm, bn, (it + 2) * BK, N, K, tid);
        CP_COMMIT();                             // (empty group near tail is fine)

        const float* a_s = smem + (it % NSTAGE) * STAGE_FLOATS;
        const float* b_s = a_s + A_TILE_FLOATS;

#pragma unroll
        for (int ks = 0; ks < 4; ++ks) {
            const int k8 = ks * 8;
            uint32_t afr[4][4], bfr[4][2];
            const int ar = lane >> 2;            // 0..7
            const int ac = lane & 3;             // 0..3
#pragma unroll
            for (int mt = 0; mt < 4; ++mt) {
                const float* ap = a_s + (wm + mt * 16 + ar) * A_PAD + k8 + ac;
                afr[mt][0] = f32_to_tf32(ap[0]);
                afr[mt][1] = f32_to_tf32(ap[8 * A_PAD]);
                afr[mt][2] = f32_to_tf32(ap[4]);
                afr[mt][3] = f32_to_tf32(ap[8 * A_PAD + 4]);
            }
            // B frag (col-major): b0 = B[k8+ac][n], b1 = B[k8+ac+4][n]
#pragma unroll
            for (int nt = 0; nt < 4; ++nt) {
                const float* bp = b_s + (k8 + ac) * B_PAD + wn + nt * 8 + ar;
                bfr[nt][0] = f32_to_tf32(bp[0]);
                bfr[nt][1] = f32_to_tf32(bp[4 * B_PAD]);
            }
#pragma unroll
            for (int mt = 0; mt < 4; ++mt)
#pragma unroll
                for (int nt = 0; nt < 4; ++nt)
                    mma_16n8k8_tf32(acc[mt][nt], afr[mt], bfr[nt]);
        }
        __syncthreads();                         // compute(it) done before stage
                                                 // (it+3) overwrites this buffer
    }

    // Epilogue: D frag layout: c0,c1 at (row=lane>>2, col=2*(lane&3)+{0,1}),
    // c2,c3 at row+8.
#pragma unroll
    for (int mt = 0; mt < 4; ++mt) {
        const int r0 = bm + wm + mt * 16 + (lane >> 2);
#pragma unroll
        for (int nt = 0; nt < 4; ++nt) {
            const int c0 = bn + wn + nt * 8 + 2 * (lane & 3);
            const float bx = bias[c0], by = bias[c0 + 1];
            float2 v0 = make_float2(acc[mt][nt][0] + bx, acc[mt][nt][1] + by);
            float2 v1 = make_float2(acc[mt][nt][2] + bx, acc[mt][nt][3] + by);
            *(float2*)(Cmat + (size_t)r0 * N + c0) = v0;
            *(float2*)(Cmat + (size_t)(r0 + 8) * N + c0) = v1;
        }
    }
}

// ---------------------------------------------------------------------------
// Chunk-parallel scan, 3 passes.
// idx layout: idx = ((b*NCHUNK + chunk) << 10) + d
// ---------------------------------------------------------------------------
__global__ __launch_bounds__(256)
void scan_pass1(const float* __restrict__ A)
{
    int idx = blockIdx.x * blockDim.x + threadIdx.x;   // 0 .. BB*NCHUNK*DD-1
    int d = idx & (DD - 1);
    int chunk = (idx >> 10) & (NCHUNK - 1);
    int b = idx >> 16;

    const float decay = 1.0f / (1.0f + expf(-A[d]));
    const float* vp = g_proj + ((size_t)b * TT + chunk * CLEN) * 2 * DD + d;

    float h = 0.0f;
#pragma unroll 8
    for (int t = 0; t < CLEN; ++t)
        h = fmaf(decay, h, __ldg(&vp[(size_t)t * 2 * DD]));
    g_carry[idx] = h;
}

__global__ __launch_bounds__(256)
void scan_pass2(const float* __restrict__ A)
{
    int idx = blockIdx.x * blockDim.x + threadIdx.x;   // 0 .. BB*DD-1
    if (idx >= BB * DD) return;
    int b = idx >> 10;
    int d = idx & (DD - 1);

    const float decay = 1.0f / (1.0f + expf(-A[d]));
    float p2 = decay * decay;
    float p4 = p2 * p2, p8 = p4 * p4, p16 = p8 * p8, p32 = p16 * p16;
    float d64 = p32 * p32;                            // decay^CLEN

    float H = 0.0f;                                   // state before chunk 0
    for (int c = 0; c < NCHUNK; ++c) {
        size_t ci = ((size_t)(b * NCHUNK + c) << 10) + d;
        float carry = g_carry[ci];
        g_carry[ci] = H;                              // overwrite with start state
        H = fmaf(d64, H, carry);
    }
}

__global__ __launch_bounds__(256)
void scan_pass3(const float* __restrict__ A, const float* __restrict__ C)
{
    int idx = blockIdx.x * blockDim.x + threadIdx.x;
    int d = idx & (DD - 1);
    int chunk = (idx >> 10) & (NCHUNK - 1);
    int b = idx >> 16;

    const float decay = 1.0f / (1.0f + expf(-A[d]));
    const float c = C[d];
    const float* vp = g_proj + ((size_t)b * TT + chunk * CLEN) * 2 * DD + d;
    const float* gp = vp + DD;
    float* yp = g_y + ((size_t)b * TT + chunk * CLEN) * DD + d;

    float h = g_carry[idx];                           // exact state h_{start-1}
#pragma unroll 4
    for (int t = 0; t < CLEN; ++t) {
        float v = __ldg(&vp[(size_t)t * 2 * DD]);
        float g = __ldg(&gp[(size_t)t * 2 * DD]);
        h = fmaf(decay, h, v);
        float gate = 1.0f / (1.0f + expf(-g));
        yp[(size_t)t * DD] = gate * c * h;
    }
}

// ---------------------------------------------------------------------------
// Launch
// ---------------------------------------------------------------------------
extern "C" void kernel_launch(void* const* d_in, const int* in_sizes, int n_in,
                              void* d_out, int out_size)
{
    const float* x     = (const float*)d_in[0];
    const float* W_in  = (const float*)d_in[1];
    const float* b_in  = (const float*)d_in[2];
    const float* A     = (const float*)d_in[3];
    const float* C     = (const float*)d_in[4];
    const float* W_out = (const float*)d_in[5];
    const float* b_out = (const float*)d_in[6];
    float*       out   = (float*)d_out;

    float *proj_ptr, *y_ptr;
    cudaGetSymbolAddress((void**)&proj_ptr, g_proj);
    cudaGetSymbolAddress((void**)&y_ptr, g_y);

    static int smem_set = 0;
    if (!smem_set) {
        cudaFuncSetAttribute(gemm_mma, cudaFuncAttributeMaxDynamicSharedMemorySize,
                             GEMM_SMEM_BYTES);
        smem_set = 1;
    }

    // GEMM1: proj = x @ W_in + b_in   (M=16384, N=2048, K=1024)
    gemm_mma<<<dim3((2 * DD) / BN, MROWS / BM), 256, GEMM_SMEM_BYTES>>>(
        x, W_in, b_in, proj_ptr, 2 * DD, DD);

    // Chunk-parallel sigmoid + SSM scan + gate + C
    {
        int n = BB * NCHUNK * DD;                 // 262144
        scan_pass1<<<n / 256, 256>>>(A);
        scan_pass2<<<(BB * DD + 255) / 256, 256>>>(A);
        scan_pass3<<<n / 256, 256>>>(A, C);
    }

    // GEMM2: out = y @ W_out + b_out  (M=16384, N=1024, K=1024)
    gemm_mma<<<dim3(DD / BN, MROWS / BM), 256, GEMM_SMEM_BYTES>>>(
        y_ptr, W_out, b_out, out, DD, DD);
}